// round 13
// baseline (speedup 1.0000x reference)
#include <cuda_runtime.h>
#include <cuda_bf16.h>

// Problem constants: P=Q=3, M=N=127, DIM=3, SU=SV=256, B=16
#define PB    16
#define PDEG  3
#define PM    127
#define PL    132          // knot vector length
#define PS    256          // samples per direction
#define PNC   128          // control points per direction
#define PDIM  3
#define PEPS  1e-8f
#define TUC   4            // u's per block
#define SROWS 8            // staged ctrl rows in shared
#define ROWF  (PNC * PDIM) // floats per ctrl row (384)
#define ROWV4 (ROWF / 4)   // float4 per ctrl row (96)
#define PFV   ((SROWS * ROWV4) / PS)   // prefetch float4 per thread (3)

// ---------------------------------------------------------------------------
// One warp normalizes one knot vector entirely in registers, writes sK.
// ---------------------------------------------------------------------------
__device__ __forceinline__ void warp_scan_knots(const float* __restrict__ knots,
                                                float* __restrict__ sK)
{
    const int lane = threadIdx.x & 31;
    const int CH = 5;                           // 32*5 >= 132
    const int base = lane * CH;
    float vch[CH];
    float run = 0.0f;
    #pragma unroll
    for (int k = 0; k < CH; k++) {
        int i = base + k;
        float x = 0.0f;
        if (i < PL) {
            x = knots[i];
            if (x < 0.0f) x = 0.0001f;
        }
        run += x;
        vch[k] = run;
    }
    float incl = run;
    #pragma unroll
    for (int off = 1; off < 32; off <<= 1) {
        float nb = __shfl_up_sync(0xffffffffu, incl, off);
        if (lane >= off) incl += nb;
    }
    const float excl = incl - run;
    const float sc0  = excl + vch[0];
    const float k0   = __shfl_sync(0xffffffffu, sc0, 0);
    const float last = __shfl_sync(0xffffffffu, incl, 31);
    const float inv  = 1.0f / (last - k0);
    #pragma unroll
    for (int k = 0; k < CH; k++) {
        int i = base + k;
        if (i < PL) sK[i] = ((excl + vch[k]) - k0) * inv;
    }
}

// span find (binary search + tie-walk, argmin semantics) + Cox-de Boor deg 3
__device__ __forceinline__ int basis_at(const float* sK, float t, float* Ni)
{
    int j;
    {
        const int cnt = PL - 2 * PDEG;          // 126
        int lo = 0, hi = cnt;
        while (lo < hi) {
            int mid = (lo + hi) >> 1;
            if (t - sK[PDEG + mid] > PEPS) lo = mid + 1;
            else hi = mid;
        }
        j = lo - 1;
        if (j < 0) j = 0;
        else {
            while (j > 0 && sK[PDEG + j - 1] == sK[PDEG + j]) j--;
        }
    }
    int span = j + PDEG;
    if (span < PDEG) span = PDEG;
    if (span > PM)   span = PM;

    Ni[0] = 1.0f; Ni[1] = 0.0f; Ni[2] = 0.0f; Ni[3] = 0.0f;
    #pragma unroll
    for (int k = 1; k <= PDEG; k++) {
        float saved = 0.0f;
        #pragma unroll
        for (int r = 0; r < PDEG; r++) {
            if (r >= k) break;
            float K1 = sK[span + r + 1];
            float K2 = sK[span + 1 - k + r];
            float denom = (K1 - t) + (t - K2);
            float temp = (denom == 0.0f) ? 0.0001f : __fdividef(Ni[r], denom);
            Ni[r] = saved + (K1 - t) * temp;
            saved = (t - K2) * temp;
        }
        Ni[k] = saved;
    }
    return span;
}

// ---------------------------------------------------------------------------
// Fused kernel: basis + prefetched ctrl staging + v-contract + 4-u fanout.
// grid = B * (PS/TUC) = 1024 blocks, blockDim = 256 (thread = vv).
// ---------------------------------------------------------------------------
__global__ void __launch_bounds__(PS)
surf_fused_kernel(const float* __restrict__ ctrl,
                  const float* __restrict__ knot_u,
                  const float* __restrict__ knot_v,
                  const float* __restrict__ u,
                  const float* __restrict__ v,
                  float* __restrict__ out)
{
    const int b   = blockIdx.x / (PS / TUC);
    const int u0  = (blockIdx.x % (PS / TUC)) * TUC;
    const int vv  = threadIdx.x;
    const int tid = threadIdx.x;
    const int wid = tid >> 5;

    __shared__ float sKv[PL];
    __shared__ float sKu[PL];
    __shared__ int   s_iu[TUC];
    __shared__ float s_nu[TUC][PDEG + 1];
    __shared__ float s_w[SROWS][TUC];
    __shared__ float sC[SROWS * ROWF];          // 12.3 KB staged ctrl rows

    // warp 0 scans v-knots; warp 1 scans u-knots then computes u-basis
    if (wid == 0) {
        warp_scan_knots(knot_v + b * PL, sKv);
    } else if (wid == 1) {
        warp_scan_knots(knot_u + b * PL, sKu);
        __syncwarp();
        const int li = tid & 31;
        if (li < TUC) {
            float nu[PDEG + 1];
            const int us = basis_at(sKu, u[u0 + li], nu);
            s_iu[li] = us - PDEG;
            #pragma unroll
            for (int p = 0; p <= PDEG; p++) s_nu[li][p] = nu[p];
        }
    }
    __syncthreads();

    const float4* cb4 = (const float4*)(ctrl + (long)b * PNC * ROWF);

    // ---- first group: prefetch rows into registers (hide LDG latency) ----
    const int rlo0 = s_iu[0];
    float4 pf[PFV];
    #pragma unroll
    for (int k = 0; k < PFV; k++) {
        const int idx = tid + k * PS;
        const int j = idx / ROWV4, t = idx % ROWV4;
        int row = rlo0 + j; if (row > PNC - 1) row = PNC - 1;
        pf[k] = __ldg(&cb4[(long)row * ROWV4 + t]);
    }

    // ---- v-basis (overlaps the LDGs above) ----
    float nv0, nv1, nv2, nv3;
    int iv;
    {
        float nv[PDEG + 1];
        iv = basis_at(sKv, v[vv], nv) - PDEG;
        nv0 = nv[0]; nv1 = nv[1]; nv2 = nv[2]; nv3 = nv[3];
    }

    float acc[TUC][PDIM];
    #pragma unroll
    for (int i = 0; i < TUC; i++) {
        acc[i][0] = 0.0f; acc[i][1] = 0.0f; acc[i][2] = 0.0f;
    }

    int done = 0;
    bool first = true;
    while (done < TUC) {
        const int rlo = s_iu[done];
        int gend = done;
        while (gend + 1 < TUC && s_iu[gend + 1] + PDEG - rlo < SROWS) gend++;

        if (!first) __syncthreads();            // protect sC/s_w reuse

        // zero-padded weight table: rows outside a u's window get 0
        if (tid < SROWS * TUC) {
            const int j = tid / TUC, i = tid % TUC;
            float w = 0.0f;
            if (i >= done && i <= gend) {
                const int p = (rlo + j) - s_iu[i];
                if (p >= 0 && p <= PDEG) w = s_nu[i][p];
            }
            s_w[j][i] = w;
        }

        if (first) {
            #pragma unroll
            for (int k = 0; k < PFV; k++)
                ((float4*)sC)[tid + k * PS] = pf[k];
        } else {                                // rare extra groups
            for (int idx = tid; idx < SROWS * ROWV4; idx += PS) {
                const int j = idx / ROWV4, t = idx % ROWV4;
                int row = rlo + j; if (row > PNC - 1) row = PNC - 1;
                ((float4*)sC)[idx] = cb4[(long)row * ROWV4 + t];
            }
        }
        __syncthreads();

        // fixed 8-row unrolled: v-contract + 4-wide fanout (zero-padded w)
        #pragma unroll
        for (int j = 0; j < SROWS; j++) {
            const float* f = sC + j * ROWF + iv * PDIM;
            const float r0 = fmaf(nv0, f[0], fmaf(nv1, f[3], fmaf(nv2, f[6],  nv3 * f[9])));
            const float r1 = fmaf(nv0, f[1], fmaf(nv1, f[4], fmaf(nv2, f[7],  nv3 * f[10])));
            const float r2 = fmaf(nv0, f[2], fmaf(nv1, f[5], fmaf(nv2, f[8],  nv3 * f[11])));
            #pragma unroll
            for (int i = 0; i < TUC; i++) {
                const float w = s_w[j][i];      // uniform broadcast LDS
                acc[i][0] = fmaf(w, r0, acc[i][0]);
                acc[i][1] = fmaf(w, r1, acc[i][1]);
                acc[i][2] = fmaf(w, r2, acc[i][2]);
            }
        }

        first = false;
        done = gend + 1;
    }

    #pragma unroll
    for (int i = 0; i < TUC; i++) {
        float* o = out + (((long)b * PS + (u0 + i)) * PS + vv) * PDIM;
        o[0] = acc[i][0];
        o[1] = acc[i][1];
        o[2] = acc[i][2];
    }
}

// ---------------------------------------------------------------------------
extern "C" void kernel_launch(void* const* d_in, const int* in_sizes, int n_in,
                              void* d_out, int out_size)
{
    const float* ctrl   = (const float*)d_in[0];  // (B, 128, 128, 3)
    const float* knot_u = (const float*)d_in[1];  // (B, 132)
    const float* knot_v = (const float*)d_in[2];  // (B, 132)
    const float* u      = (const float*)d_in[3];  // (256,)
    const float* v      = (const float*)d_in[4];  // (256,)
    float* out = (float*)d_out;                   // (B, 256, 256, 3)

    surf_fused_kernel<<<PB * (PS / TUC), PS>>>(ctrl, knot_u, knot_v, u, v, out);
}